// round 13
// baseline (speedup 1.0000x reference)
#include <cuda_runtime.h>
#include <cuda_fp16.h>
#include <math.h>
#include <stdint.h>

#define B_   64
#define C_   1000
#define F_   2048
#define CP   1024
#define NB   148
#define KSA  4
#define KSM  4
#define KSC  4
#define KT   32
#define GA   (64 * 40)          // halves per tile array (row stride 40)
#define GRP  (3 * GA)           // Ah, Al, Bh per buffer
typedef unsigned long long ull;

// ---------------- scratch ----------------
__device__ __align__(256) float g_p_dot[KSA][B_ * CP];
__device__ __align__(256) float g_p_hall[KSA][B_ * CP];
__device__ __align__(256) float g_p_sel[KSA][B_ * F_];
__device__ __align__(256) float g_p_mem[KSM][B_ * F_];
__device__ __align__(256) float g_p_cos[KSC][B_ * CP];
__device__ __align__(256) __half g_xh[B_ * F_];
__device__ __align__(256) __half g_xl[B_ * F_];
__device__ __align__(256) __half g_vmh[B_ * CP];
__device__ __align__(256) __half g_vml[B_ * CP];
__device__ __align__(256) __half g_fh[B_ * F_];
__device__ __align__(256) __half g_fl[B_ * F_];
__device__ float g_cn2[CP];
__device__ float g_wn[CP];
__device__ float g_xn2[B_];
__device__ float g_reach[B_];
__device__ float g_scale[B_];
__device__ float g_n2p[128];
__device__ unsigned int g_arr[8];
__device__ unsigned int g_flag[8];

// ---------------- barriers / async ----------------
__device__ __forceinline__ void gbar(int id) {
    asm volatile("bar.sync %0, 256;" :: "r"(id) : "memory");
}
__device__ __forceinline__ uint32_t sm32(const void* p) {
    return (uint32_t)__cvta_generic_to_shared(p);
}
#define CPA16(sm, gp)  asm volatile("cp.async.cg.shared.global [%0], [%1], 16;" :: "r"(sm), "l"(gp))
#define CPCOMMIT()     asm volatile("cp.async.commit_group;" ::: "memory")
#define CPWAIT1()      asm volatile("cp.async.wait_group 1;" ::: "memory")

__device__ __forceinline__ void grid_sync(int s) {
    __threadfence();
    __syncthreads();
    if (threadIdx.x == 0) {
        unsigned int before = atomicOr(&g_flag[s], 0u);
        unsigned int old = atomicAdd(&g_arr[s], 1u);
        if (old == NB - 1) {
            g_arr[s] = 0;
            __threadfence();
            atomicAdd(&g_flag[s], 1u);
        } else {
            while (atomicOr(&g_flag[s], 0u) == before) __nanosleep(32);
        }
    }
    __syncthreads();
    __threadfence();
}

// ---------------- block reductions (1024 threads) ----------------
__device__ __forceinline__ float blk_sum(float v, float* red) {
#pragma unroll
    for (int o = 16; o; o >>= 1) v += __shfl_xor_sync(0xffffffffu, v, o);
    if ((threadIdx.x & 31) == 0) red[threadIdx.x >> 5] = v;
    __syncthreads();
    if (threadIdx.x < 32) {
        float s = red[threadIdx.x];
#pragma unroll
        for (int o = 16; o; o >>= 1) s += __shfl_xor_sync(0xffffffffu, s, o);
        if (threadIdx.x == 0) red[0] = s;
    }
    __syncthreads();
    float r = red[0];
    __syncthreads();
    return r;
}
__device__ __forceinline__ float blk_min(float v, float* red) {
#pragma unroll
    for (int o = 16; o; o >>= 1) v = fminf(v, __shfl_xor_sync(0xffffffffu, v, o));
    if ((threadIdx.x & 31) == 0) red[threadIdx.x >> 5] = v;
    __syncthreads();
    if (threadIdx.x < 32) {
        float s = red[threadIdx.x];
#pragma unroll
        for (int o = 16; o; o >>= 1) s = fminf(s, __shfl_xor_sync(0xffffffffu, s, o));
        if (threadIdx.x == 0) red[0] = s;
    }
    __syncthreads();
    float r = red[0];
    __syncthreads();
    return r;
}
__device__ __forceinline__ float blk_max(float v, float* red) {
#pragma unroll
    for (int o = 16; o; o >>= 1) v = fmaxf(v, __shfl_xor_sync(0xffffffffu, v, o));
    if ((threadIdx.x & 31) == 0) red[threadIdx.x >> 5] = v;
    __syncthreads();
    if (threadIdx.x < 32) {
        float s = red[threadIdx.x];
#pragma unroll
        for (int o = 16; o; o >>= 1) s = fmaxf(s, __shfl_xor_sync(0xffffffffu, s, o));
        if (threadIdx.x == 0) red[0] = s;
    }
    __syncthreads();
    float r = red[0];
    __syncthreads();
    return r;
}

// ---------------- fp16 helpers ----------------
__device__ __forceinline__ uint32_t f16pack(float lo, float hi) {
    uint32_t r;
    asm("cvt.rn.f16x2.f32 %0, %1, %2;" : "=r"(r) : "f"(hi), "f"(lo));
    return r;
}
__device__ __forceinline__ void hilo1(float v, __half& h, __half& l) {
    h = __float2half_rn(v);
    l = __float2half_rn(v - __half2float(h));
}
__device__ __forceinline__ void mma16816(float* d,
                                         uint32_t a0, uint32_t a1, uint32_t a2, uint32_t a3,
                                         uint32_t b0, uint32_t b1) {
    asm volatile("mma.sync.aligned.m16n8k16.row.col.f32.f16.f16.f32 "
        "{%0,%1,%2,%3}, {%4,%5,%6,%7}, {%8,%9}, {%0,%1,%2,%3};"
        : "+f"(d[0]), "+f"(d[1]), "+f"(d[2]), "+f"(d[3])
        : "r"(a0), "r"(a1), "r"(a2), "r"(a3), "r"(b0), "r"(b1));
}

// ---------------- mma over one 64x64x32 tile: acc += (Ah+Al)*Bh ----------------
__device__ __forceinline__ void tile_f16(const __half* buf, int m0, int nh,
                                         int fr, int fc, float acc[4][4]) {
    const __half* Ah = buf;
    const __half* Al = buf + GA;
    const __half* Bh = buf + 2 * GA;
#pragma unroll
    for (int kk = 0; kk < 2; kk++) {
        const int kc = kk * 16 + fc;
        uint32_t ah0 = *(const uint32_t*)&Ah[(m0 + fr) * 40 + kc];
        uint32_t ah1 = *(const uint32_t*)&Ah[(m0 + fr + 8) * 40 + kc];
        uint32_t ah2 = *(const uint32_t*)&Ah[(m0 + fr) * 40 + kc + 8];
        uint32_t ah3 = *(const uint32_t*)&Ah[(m0 + fr + 8) * 40 + kc + 8];
        uint32_t al0 = *(const uint32_t*)&Al[(m0 + fr) * 40 + kc];
        uint32_t al1 = *(const uint32_t*)&Al[(m0 + fr + 8) * 40 + kc];
        uint32_t al2 = *(const uint32_t*)&Al[(m0 + fr) * 40 + kc + 8];
        uint32_t al3 = *(const uint32_t*)&Al[(m0 + fr + 8) * 40 + kc + 8];
#pragma unroll
        for (int nt = 0; nt < 4; nt++) {
            const int bn = (nh + nt * 8 + fr) * 40;
            uint32_t bh0 = *(const uint32_t*)&Bh[bn + kc];
            uint32_t bh1 = *(const uint32_t*)&Bh[bn + kc + 8];
            mma16816(acc[nt], ah0, ah1, ah2, ah3, bh0, bh1);
            mma16816(acc[nt], al0, al1, al2, al3, bh0, bh1);
        }
    }
}

__device__ __forceinline__ void store_acc(float* __restrict__ P, int ldp, int n0,
                                          int m0, int nh, int fr, int fc,
                                          float acc[4][4]) {
#pragma unroll
    for (int nt = 0; nt < 4; nt++) {
        const int n = n0 + nh + nt * 8 + fc;
        *(float2*)&P[(size_t)(m0 + fr) * ldp + n]     = make_float2(acc[nt][0], acc[nt][1]);
        *(float2*)&P[(size_t)(m0 + fr + 8) * ldp + n] = make_float2(acc[nt][2], acc[nt][3]);
    }
}

// NT: P = A(fp16 h/l precomputed) @ B(fp32, cvt hi-only)^T. 3-deep cp.async pipeline.
__device__ __forceinline__ void group_nt_f16(const __half* __restrict__ Ahg,
                                             const __half* __restrict__ Alg, int lda,
                                             const float* __restrict__ Bm, int ldb,
                                             float* __restrict__ P, int ldp,
                                             int Nn, int n0, int k0, int klen,
                                             __half* gsm, int gt, int barid) {
    const int lane = gt & 31, wg = gt >> 5;
    const int m0 = (wg & 3) * 16, nh = (wg >> 2) * 32;
    const int fr = lane >> 2, fc = (lane & 3) * 2;
    const int row = gt >> 2, kq = (gt & 3) * 8;
    const bool bv = (n0 + row) < Nn;
    const __half* Ah_p = Ahg + (size_t)row * lda + k0 + kq;
    const __half* Al_p = Alg + (size_t)row * lda + k0 + kq;
    const float*  B_p  = Bm + (size_t)(n0 + row) * ldb + k0 + kq;
    const int T = klen >> 5;
    const uint32_t base32 = sm32(gsm);
    const uint32_t offA = (uint32_t)(row * 40 + kq) * 2;

    float acc[4][4];
#pragma unroll
    for (int i = 0; i < 4; i++)
#pragma unroll
        for (int j = 0; j < 4; j++) acc[i][j] = 0.f;

    float4 pb0, pb1;
    auto ldB = [&](int t) {
        if (bv) { pb0 = *(const float4*)(B_p + t * KT); pb1 = *(const float4*)(B_p + t * KT + 4); }
        else    { pb0 = make_float4(0,0,0,0); pb1 = pb0; }
    };
    auto stB = [&](int bufi) {
        uint4 bp = make_uint4(f16pack(pb0.x, pb0.y), f16pack(pb0.z, pb0.w),
                              f16pack(pb1.x, pb1.y), f16pack(pb1.z, pb1.w));
        *(uint4*)(gsm + bufi * GRP + 2 * GA + row * 40 + kq) = bp;
    };
    auto cpA = [&](int bufi, int t) {
        uint32_t b = base32 + (uint32_t)bufi * (GRP * 2) + offA;
        CPA16(b, Ah_p + t * KT);
        CPA16(b + GA * 2, Al_p + t * KT);
    };

    cpA(0, 0); CPCOMMIT();
    cpA(1, 1); CPCOMMIT();
    ldB(0); stB(0);
    ldB(1);
    CPWAIT1();
    gbar(barid);

    int cur = 0;
    for (int t = 0; t < T; t++) {
        int nx2 = cur + 2; if (nx2 >= 3) nx2 -= 3;
        if (t + 2 < T) cpA(nx2, t + 2);
        CPCOMMIT();
        tile_f16(gsm + cur * GRP, m0, nh, fr, fc, acc);
        if (t + 1 < T) {
            int nx = cur + 1; if (nx == 3) nx = 0;
            stB(nx);
            if (t + 2 < T) ldB(t + 2);
            CPWAIT1();
            gbar(barid);
        }
        cur = cur + 1; if (cur == 3) cur = 0;
    }
    store_acc(P, ldp, n0, m0, nh, fr, fc, acc);
}

// NN: P = A(fp16 h/l) @ B(fp32 k-major, cvt + transpose hi-only). 3-deep pipeline.
__device__ __forceinline__ void group_nn_f16(const __half* __restrict__ Ahg,
                                             const __half* __restrict__ Alg, int lda,
                                             const float* __restrict__ Bm, int ldb,
                                             float* __restrict__ P, int ldp,
                                             int n0, int k0, int klen,
                                             __half* gsm, int gt, int barid) {
    const int lane = gt & 31, wg = gt >> 5;
    const int m0 = (wg & 3) * 16, nh = (wg >> 2) * 32;
    const int fr = lane >> 2, fc = (lane & 3) * 2;
    const int row = gt >> 2, kq = (gt & 3) * 8;
    const int k2 = (gt & 15) * 2, nq = (gt >> 4) * 4;
    const __half* Ah_p = Ahg + (size_t)row * lda + k0 + kq;
    const __half* Al_p = Alg + (size_t)row * lda + k0 + kq;
    const int T = klen >> 5;
    const uint32_t base32 = sm32(gsm);
    const uint32_t offA = (uint32_t)(row * 40 + kq) * 2;

    float acc[4][4];
#pragma unroll
    for (int i = 0; i < 4; i++)
#pragma unroll
        for (int j = 0; j < 4; j++) acc[i][j] = 0.f;

    float4 pb0, pb1;
    auto ldB = [&](int t) {
        int kr0 = k0 + t * KT + k2;
        pb0 = (kr0 < C_)     ? *(const float4*)&Bm[(size_t)kr0 * ldb + n0 + nq]       : make_float4(0,0,0,0);
        pb1 = (kr0 + 1 < C_) ? *(const float4*)&Bm[(size_t)(kr0 + 1) * ldb + n0 + nq] : make_float4(0,0,0,0);
    };
    auto stB = [&](int bufi) {
        __half* Bh = gsm + bufi * GRP + 2 * GA;
        *(uint32_t*)&Bh[(nq + 0) * 40 + k2] = f16pack(pb0.x, pb1.x);
        *(uint32_t*)&Bh[(nq + 1) * 40 + k2] = f16pack(pb0.y, pb1.y);
        *(uint32_t*)&Bh[(nq + 2) * 40 + k2] = f16pack(pb0.z, pb1.z);
        *(uint32_t*)&Bh[(nq + 3) * 40 + k2] = f16pack(pb0.w, pb1.w);
    };
    auto cpA = [&](int bufi, int t) {
        uint32_t b = base32 + (uint32_t)bufi * (GRP * 2) + offA;
        CPA16(b, Ah_p + t * KT);
        CPA16(b + GA * 2, Al_p + t * KT);
    };

    cpA(0, 0); CPCOMMIT();
    cpA(1, 1); CPCOMMIT();
    ldB(0); stB(0);
    ldB(1);
    CPWAIT1();
    gbar(barid);

    int cur = 0;
    for (int t = 0; t < T; t++) {
        int nx2 = cur + 2; if (nx2 >= 3) nx2 -= 3;
        if (t + 2 < T) cpA(nx2, t + 2);
        CPCOMMIT();
        tile_f16(gsm + cur * GRP, m0, nh, fr, fc, acc);
        if (t + 1 < T) {
            int nx = cur + 1; if (nx == 3) nx = 0;
            stB(nx);
            if (t + 2 < T) ldB(t + 2);
            CPWAIT1();
            gbar(barid);
        }
        cur = cur + 1; if (cur == 3) cur = 0;
    }
    store_acc(P, ldp, n0, m0, nh, fr, fc, acc);
}

// ---------------- the single fused persistent kernel ----------------
__global__ void __launch_bounds__(1024, 1)
fused_all(const float* __restrict__ x,
          const float* __restrict__ centroids,
          const float* __restrict__ W_hall,
          const float* __restrict__ b_hall,
          const float* __restrict__ W_sel,
          const float* __restrict__ b_sel,
          const float* __restrict__ W_cos,
          float* __restrict__ out, int writeFeat) {
    extern __shared__ __align__(16) __half dsm[];   // 4 groups * 3 buffers * GRP
    __shared__ float red[32];
    const int tid = threadIdx.x, bid = blockIdx.x;
    const int gid = tid >> 8, gt = tid & 255, barid = gid + 1;
    __half* gsm = dsm + gid * 3 * GRP;

    // ===== S0a: x -> fp16 hi/lo =====
    {
        const int i = bid * 1024 + tid;
        if (i < B_ * F_) {
            __half h, l;
            hilo1(x[i], h, l);
            g_xh[i] = h; g_xl[i] = l;
        }
    }
    // ===== S0b: row norms (one row per warp) =====
    {
        const int gw = bid * 32 + (tid >> 5);
        const int lane = tid & 31;
        if (gw < 2064) {
            const float* src; int mode, idx;
            if (gw < 1000)      { src = centroids + (size_t)gw * F_;      mode = 0; idx = gw; }
            else if (gw < 2000) { src = W_cos + (size_t)(gw - 1000) * F_; mode = 1; idx = gw - 1000; }
            else                { src = x + (size_t)(gw - 2000) * F_;     mode = 2; idx = gw - 2000; }
            const float4* s4 = (const float4*)src;
            float s = 0.f;
            for (int i = lane; i < F_ / 4; i += 32) {
                float4 v = s4[i];
                s += v.x * v.x + v.y * v.y + v.z * v.z + v.w * v.w;
            }
#pragma unroll
            for (int o = 16; o; o >>= 1) s += __shfl_xor_sync(0xffffffffu, s, o);
            if (lane == 0) {
                if (mode == 0)      g_cn2[idx] = s;
                else if (mode == 1) g_wn[idx]  = sqrtf(s);
                else                g_xn2[idx] = s;
            }
        }
    }
    grid_sync(0);

    // ===== S1: mega GEMMs x @ [centroids; W_hall; W_sel]^T  (256 items, klen 512) =====
    {
        const int item = bid * 4 + gid;
        if (item < 64 * KSA) {
            const int t = item & 63, ks = item >> 6;
            const float* Bm; float* P; int Nn, n0, ldp;
            if (t < 16)      { Bm = centroids; P = g_p_dot[ks];  Nn = C_; n0 = t * 64;        ldp = CP; }
            else if (t < 32) { Bm = W_hall;    P = g_p_hall[ks]; Nn = C_; n0 = (t - 16) * 64; ldp = CP; }
            else             { Bm = W_sel;     P = g_p_sel[ks];  Nn = F_; n0 = (t - 32) * 64; ldp = F_; }
            group_nt_f16(g_xh, g_xl, F_, Bm, F_, P, ldp, Nn, n0, ks * 512, 512, gsm, gt, barid);
        }
    }
    grid_sync(1);

    // ===== S2: reduce dot/hall, min-dist, softmax, reachability (64 blocks) =====
    if (bid < B_) {
        const int b = bid;
        const int c0 = tid * 2;
        const bool val = (tid < 500);
        float hv0 = -1e30f, hv1 = -1e30f, d2m = 1e30f;
        if (val) {
            float2 dot = make_float2(0.f, 0.f), h = make_float2(0.f, 0.f);
#pragma unroll
            for (int s = 0; s < KSA; s++) {
                float2 d = *(const float2*)&g_p_dot[s][b * CP + c0];
                float2 hh = *(const float2*)&g_p_hall[s][b * CP + c0];
                dot.x += d.x; dot.y += d.y; h.x += hh.x; h.y += hh.y;
            }
            float2 bh = *(const float2*)&b_hall[c0];
            hv0 = h.x + bh.x; hv1 = h.y + bh.y;
            float xn2 = g_xn2[b];
            float d20 = xn2 + g_cn2[c0] - 2.f * dot.x;
            float d21 = xn2 + g_cn2[c0 + 1] - 2.f * dot.y;
            d2m = fminf(d20, d21);
        }
        float md2 = blk_min(d2m, red);
        float mh  = blk_max(fmaxf(hv0, hv1), red);
        float e0 = val ? __expf(hv0 - mh) : 0.f;
        float e1 = val ? __expf(hv1 - mh) : 0.f;
        float se = blk_sum(e0 + e1, red);
        if (tid < 512) {
            float inv = 1.f / se;
            float w0 = val ? e0 * inv : 0.f;
            float w1 = val ? e1 * inv : 0.f;
            uint32_t hp = f16pack(w0, w1);
            *(uint32_t*)&g_vmh[b * CP + c0] = hp;
            __half2 hh = *(__half2*)&hp;
            float l0 = w0 - __half2float(__low2half(hh));
            float l1 = w1 - __half2float(__high2half(hh));
            *(uint32_t*)&g_vml[b * CP + c0] = f16pack(l0, l1);
        }
        if (tid == 0) g_reach[b] = 10.f / sqrtf(fmaxf(md2, 1e-30f));
    }
    grid_sync(2);

    // ===== S3: memory_feature = vm @ centroids  (128 items, klen 256) =====
    {
        const int item = bid * 4 + gid;
        if (item < 32 * KSM) {
            const int nt = item & 31, ks = item >> 5;
            group_nn_f16(g_vmh, g_vml, CP, centroids, F_, g_p_mem[ks], F_,
                         nt * 64, ks * 256, 256, gsm, gt, barid);
        }
    }
    grid_sync(3);

    // ===== S4: feat = reach*(x + tanh(sel)*mem) on 128 blocks (half row each) =====
    if (bid < 128) {
        const int b = bid >> 1;
        const int f = (bid & 1) * 1024 + tid;
        const float reach = g_reach[b];
        float mem = 0.f, sz = 0.f;
#pragma unroll
        for (int s = 0; s < KSM; s++) mem += g_p_mem[s][b * F_ + f];
#pragma unroll
        for (int s = 0; s < KSA; s++) sz  += g_p_sel[s][b * F_ + f];
        float sel  = tanhf(sz + b_sel[f]);
        float xv   = x[(size_t)b * F_ + f];
        float inf  = sel * mem;
        float feat = reach * (xv + inf);
        __half fh, fl;
        hilo1(feat, fh, fl);
        g_fh[b * F_ + f] = fh;
        g_fl[b * F_ + f] = fl;
        if (writeFeat) {
            out[64000 + b * F_ + f]  = xv;   // direct_feature
            out[195072 + b * F_ + f] = inf;  // infused_feature
        }
        float n2 = blk_sum(feat * feat, red);
        if (tid == 0) g_n2p[bid] = n2;
    }
    grid_sync(4);

    // ===== S5: cos logits GEMM feat @ W_cos^T (64 items, klen 512) + scale reduce =====
    {
        const int item = bid * 4 + gid;
        if (item < 16 * KSC) {
            const int nt = item & 15, ks = item >> 4;
            group_nt_f16(g_fh, g_fl, F_, W_cos, F_, g_p_cos[ks], CP, C_,
                         nt * 64, ks * 512, 512, gsm, gt, barid);
        }
    }
    if (bid == NB - 1 && tid < B_) {
        float n2 = g_n2p[2 * tid] + g_n2p[2 * tid + 1];
        g_scale[tid] = 16.f / (1.f + sqrtf(n2));
    }
    grid_sync(5);

    // ===== S6: final scaled logits =====
    {
        const int i = bid * 1024 + tid;
        if (i < B_ * C_) {
            const int b = i / C_, c = i - b * C_;
            float s = 0.f;
#pragma unroll
            for (int ss = 0; ss < KSC; ss++) s += g_p_cos[ss][b * CP + c];
            out[i] = s * g_scale[b] / g_wn[c];
        }
    }
}

// ================= launch =================
#define DSM_BYTES (4 * 3 * GRP * 2)   // 4 groups * 3 buffers * (3*64*40) halves = 184320 B

extern "C" void kernel_launch(void* const* d_in, const int* in_sizes, int n_in,
                              void* d_out, int out_size) {
    const float* x         = (const float*)d_in[0];
    const float* centroids = (const float*)d_in[1];
    const float* W_hall    = (const float*)d_in[2];
    const float* b_hall    = (const float*)d_in[3];
    const float* W_sel     = (const float*)d_in[4];
    const float* b_sel     = (const float*)d_in[5];
    const float* W_cos     = (const float*)d_in[6];
    float* out = (float*)d_out;

    cudaFuncSetAttribute(fused_all, cudaFuncAttributeMaxDynamicSharedMemorySize, DSM_BYTES);

    int writeFeat = (out_size >= 326144) ? 1 : 0;
    fused_all<<<NB, 1024, DSM_BYTES>>>(x, centroids, W_hall, b_hall, W_sel, b_sel, W_cos,
                                       out, writeFeat);
}

// round 14
// speedup vs baseline: 1.8165x; 1.8165x over previous
#include <cuda_runtime.h>
#include <cuda_fp16.h>
#include <math.h>
#include <stdint.h>

#define B_   64
#define C_   1000
#define F_   2048
#define CP   1024
#define NB   148
#define KSA  8
#define KSM  16
#define KSC  32
#define KT   32
#define GA   (64 * 40)          // halves per tile array (row stride 40)
#define GRP  (3 * GA)           // Ah, Al, Bh per buffer
typedef unsigned long long ull;

// ---------------- scratch ----------------
__device__ __align__(256) float g_p_dot[KSA][B_ * CP];
__device__ __align__(256) float g_p_hall[KSA][B_ * CP];
__device__ __align__(256) float g_p_sel[KSA][B_ * F_];
__device__ __align__(256) float g_p_mem[KSM][B_ * F_];
__device__ __align__(256) float g_p_cos[KSC][B_ * CP];
__device__ __align__(256) __half g_xh[B_ * F_];
__device__ __align__(256) __half g_xl[B_ * F_];
__device__ __align__(256) __half g_vmh[B_ * CP];
__device__ __align__(256) __half g_vml[B_ * CP];
__device__ __align__(256) __half g_fh[B_ * F_];
__device__ __align__(256) __half g_fl[B_ * F_];
__device__ float g_cn2[CP];
__device__ float g_wn[CP];
__device__ float g_xn2[B_];
__device__ float g_reach[B_];
__device__ float g_scale[B_];
__device__ float g_n2p[128];
__device__ unsigned int g_arr[8];
__device__ unsigned int g_flag[8];

// ---------------- barriers / async ----------------
__device__ __forceinline__ void gbar(int id) {
    asm volatile("bar.sync %0, 256;" :: "r"(id) : "memory");
}
__device__ __forceinline__ uint32_t sm32(const void* p) {
    return (uint32_t)__cvta_generic_to_shared(p);
}
#define CPA16(sm, gp)  asm volatile("cp.async.cg.shared.global [%0], [%1], 16;" :: "r"(sm), "l"(gp))
#define CPCOMMIT()     asm volatile("cp.async.commit_group;" ::: "memory")
#define CPWAIT1()      asm volatile("cp.async.wait_group 1;" ::: "memory")

__device__ __forceinline__ void grid_sync(int s) {
    __threadfence();
    __syncthreads();
    if (threadIdx.x == 0) {
        unsigned int before = atomicOr(&g_flag[s], 0u);
        unsigned int old = atomicAdd(&g_arr[s], 1u);
        if (old == NB - 1) {
            g_arr[s] = 0;
            __threadfence();
            atomicAdd(&g_flag[s], 1u);
        } else {
            while (atomicOr(&g_flag[s], 0u) == before) __nanosleep(32);
        }
    }
    __syncthreads();
    __threadfence();
}

// ---------------- block reductions (1024 threads) ----------------
__device__ __forceinline__ float blk_sum(float v, float* red) {
#pragma unroll
    for (int o = 16; o; o >>= 1) v += __shfl_xor_sync(0xffffffffu, v, o);
    if ((threadIdx.x & 31) == 0) red[threadIdx.x >> 5] = v;
    __syncthreads();
    if (threadIdx.x < 32) {
        float s = red[threadIdx.x];
#pragma unroll
        for (int o = 16; o; o >>= 1) s += __shfl_xor_sync(0xffffffffu, s, o);
        if (threadIdx.x == 0) red[0] = s;
    }
    __syncthreads();
    float r = red[0];
    __syncthreads();
    return r;
}
__device__ __forceinline__ float blk_min(float v, float* red) {
#pragma unroll
    for (int o = 16; o; o >>= 1) v = fminf(v, __shfl_xor_sync(0xffffffffu, v, o));
    if ((threadIdx.x & 31) == 0) red[threadIdx.x >> 5] = v;
    __syncthreads();
    if (threadIdx.x < 32) {
        float s = red[threadIdx.x];
#pragma unroll
        for (int o = 16; o; o >>= 1) s = fminf(s, __shfl_xor_sync(0xffffffffu, s, o));
        if (threadIdx.x == 0) red[0] = s;
    }
    __syncthreads();
    float r = red[0];
    __syncthreads();
    return r;
}
__device__ __forceinline__ float blk_max(float v, float* red) {
#pragma unroll
    for (int o = 16; o; o >>= 1) v = fmaxf(v, __shfl_xor_sync(0xffffffffu, v, o));
    if ((threadIdx.x & 31) == 0) red[threadIdx.x >> 5] = v;
    __syncthreads();
    if (threadIdx.x < 32) {
        float s = red[threadIdx.x];
#pragma unroll
        for (int o = 16; o; o >>= 1) s = fmaxf(s, __shfl_xor_sync(0xffffffffu, s, o));
        if (threadIdx.x == 0) red[0] = s;
    }
    __syncthreads();
    float r = red[0];
    __syncthreads();
    return r;
}

// ---------------- fp16 helpers ----------------
__device__ __forceinline__ uint32_t f16pack(float lo, float hi) {
    uint32_t r;
    asm("cvt.rn.f16x2.f32 %0, %1, %2;" : "=r"(r) : "f"(hi), "f"(lo));
    return r;
}
__device__ __forceinline__ void hilo1(float v, __half& h, __half& l) {
    h = __float2half_rn(v);
    l = __float2half_rn(v - __half2float(h));
}
__device__ __forceinline__ void mma16816(float* d,
                                         uint32_t a0, uint32_t a1, uint32_t a2, uint32_t a3,
                                         uint32_t b0, uint32_t b1) {
    asm volatile("mma.sync.aligned.m16n8k16.row.col.f32.f16.f16.f32 "
        "{%0,%1,%2,%3}, {%4,%5,%6,%7}, {%8,%9}, {%0,%1,%2,%3};"
        : "+f"(d[0]), "+f"(d[1]), "+f"(d[2]), "+f"(d[3])
        : "r"(a0), "r"(a1), "r"(a2), "r"(a3), "r"(b0), "r"(b1));
}

// ---------------- row sum-of-squares by one warp ----------------
__device__ __forceinline__ float warp_row_ss(const float* __restrict__ src, int lane) {
    const float4* s4 = (const float4*)src;
    float s = 0.f;
#pragma unroll
    for (int i = 0; i < F_ / 4 / 32; i++) {
        float4 v = s4[lane + i * 32];
        s += v.x * v.x + v.y * v.y + v.z * v.z + v.w * v.w;
    }
#pragma unroll
    for (int o = 16; o; o >>= 1) s += __shfl_xor_sync(0xffffffffu, s, o);
    return s;
}

// ---------------- mma over one 64x64x32 tile: acc += (Ah+Al)*Bh ----------------
__device__ __forceinline__ void tile_f16(const __half* buf, int m0, int nh,
                                         int fr, int fc, float acc[4][4]) {
    const __half* Ah = buf;
    const __half* Al = buf + GA;
    const __half* Bh = buf + 2 * GA;
#pragma unroll
    for (int kk = 0; kk < 2; kk++) {
        const int kc = kk * 16 + fc;
        uint32_t ah0 = *(const uint32_t*)&Ah[(m0 + fr) * 40 + kc];
        uint32_t ah1 = *(const uint32_t*)&Ah[(m0 + fr + 8) * 40 + kc];
        uint32_t ah2 = *(const uint32_t*)&Ah[(m0 + fr) * 40 + kc + 8];
        uint32_t ah3 = *(const uint32_t*)&Ah[(m0 + fr + 8) * 40 + kc + 8];
        uint32_t al0 = *(const uint32_t*)&Al[(m0 + fr) * 40 + kc];
        uint32_t al1 = *(const uint32_t*)&Al[(m0 + fr + 8) * 40 + kc];
        uint32_t al2 = *(const uint32_t*)&Al[(m0 + fr) * 40 + kc + 8];
        uint32_t al3 = *(const uint32_t*)&Al[(m0 + fr + 8) * 40 + kc + 8];
#pragma unroll
        for (int nt = 0; nt < 4; nt++) {
            const int bn = (nh + nt * 8 + fr) * 40;
            uint32_t bh0 = *(const uint32_t*)&Bh[bn + kc];
            uint32_t bh1 = *(const uint32_t*)&Bh[bn + kc + 8];
            mma16816(acc[nt], ah0, ah1, ah2, ah3, bh0, bh1);
            mma16816(acc[nt], al0, al1, al2, al3, bh0, bh1);
        }
    }
}

__device__ __forceinline__ void store_acc(float* __restrict__ P, int ldp, int n0,
                                          int m0, int nh, int fr, int fc,
                                          float acc[4][4]) {
#pragma unroll
    for (int nt = 0; nt < 4; nt++) {
        const int n = n0 + nh + nt * 8 + fc;
        *(float2*)&P[(size_t)(m0 + fr) * ldp + n]     = make_float2(acc[nt][0], acc[nt][1]);
        *(float2*)&P[(size_t)(m0 + fr + 8) * ldp + n] = make_float2(acc[nt][2], acc[nt][3]);
    }
}

// NT: P = A(fp16 h/l precomputed) @ B(fp32, cvt hi-only)^T. 3-deep cp.async pipeline.
__device__ __forceinline__ void group_nt_f16(const __half* __restrict__ Ahg,
                                             const __half* __restrict__ Alg, int lda,
                                             const float* __restrict__ Bm, int ldb,
                                             float* __restrict__ P, int ldp,
                                             int Nn, int n0, int k0, int klen,
                                             __half* gsm, int gt, int barid) {
    const int lane = gt & 31, wg = gt >> 5;
    const int m0 = (wg & 3) * 16, nh = (wg >> 2) * 32;
    const int fr = lane >> 2, fc = (lane & 3) * 2;
    const int row = gt >> 2, kq = (gt & 3) * 8;
    const bool bv = (n0 + row) < Nn;
    const __half* Ah_p = Ahg + (size_t)row * lda + k0 + kq;
    const __half* Al_p = Alg + (size_t)row * lda + k0 + kq;
    const float*  B_p  = Bm + (size_t)(n0 + row) * ldb + k0 + kq;
    const int T = klen >> 5;
    const uint32_t base32 = sm32(gsm);
    const uint32_t offA = (uint32_t)(row * 40 + kq) * 2;

    float acc[4][4];
#pragma unroll
    for (int i = 0; i < 4; i++)
#pragma unroll
        for (int j = 0; j < 4; j++) acc[i][j] = 0.f;

    float4 pb0, pb1;
    auto ldB = [&](int t) {
        if (bv) { pb0 = *(const float4*)(B_p + t * KT); pb1 = *(const float4*)(B_p + t * KT + 4); }
        else    { pb0 = make_float4(0,0,0,0); pb1 = pb0; }
    };
    auto stB = [&](int bufi) {
        uint4 bp = make_uint4(f16pack(pb0.x, pb0.y), f16pack(pb0.z, pb0.w),
                              f16pack(pb1.x, pb1.y), f16pack(pb1.z, pb1.w));
        *(uint4*)(gsm + bufi * GRP + 2 * GA + row * 40 + kq) = bp;
    };
    auto cpA = [&](int bufi, int t) {
        uint32_t b = base32 + (uint32_t)bufi * (GRP * 2) + offA;
        CPA16(b, Ah_p + t * KT);
        CPA16(b + GA * 2, Al_p + t * KT);
    };

    cpA(0, 0); CPCOMMIT();
    cpA(1, 1); CPCOMMIT();
    ldB(0); stB(0);
    ldB(1);
    CPWAIT1();
    gbar(barid);

    int cur = 0;
    for (int t = 0; t < T; t++) {
        int nx2 = cur + 2; if (nx2 >= 3) nx2 -= 3;
        if (t + 2 < T) cpA(nx2, t + 2);
        CPCOMMIT();
        tile_f16(gsm + cur * GRP, m0, nh, fr, fc, acc);
        if (t + 1 < T) {
            int nx = cur + 1; if (nx == 3) nx = 0;
            stB(nx);
            if (t + 2 < T) ldB(t + 2);
            CPWAIT1();
            gbar(barid);
        }
        cur = cur + 1; if (cur == 3) cur = 0;
    }
    store_acc(P, ldp, n0, m0, nh, fr, fc, acc);
}

// NN: P = A(fp16 h/l) @ B(fp32 k-major, cvt + transpose hi-only). 3-deep pipeline.
__device__ __forceinline__ void group_nn_f16(const __half* __restrict__ Ahg,
                                             const __half* __restrict__ Alg, int lda,
                                             const float* __restrict__ Bm, int ldb,
                                             float* __restrict__ P, int ldp,
                                             int n0, int k0, int klen,
                                             __half* gsm, int gt, int barid) {
    const int lane = gt & 31, wg = gt >> 5;
    const int m0 = (wg & 3) * 16, nh = (wg >> 2) * 32;
    const int fr = lane >> 2, fc = (lane & 3) * 2;
    const int row = gt >> 2, kq = (gt & 3) * 8;
    const int k2 = (gt & 15) * 2, nq = (gt >> 4) * 4;
    const __half* Ah_p = Ahg + (size_t)row * lda + k0 + kq;
    const __half* Al_p = Alg + (size_t)row * lda + k0 + kq;
    const int T = klen >> 5;
    const uint32_t base32 = sm32(gsm);
    const uint32_t offA = (uint32_t)(row * 40 + kq) * 2;

    float acc[4][4];
#pragma unroll
    for (int i = 0; i < 4; i++)
#pragma unroll
        for (int j = 0; j < 4; j++) acc[i][j] = 0.f;

    float4 pb0, pb1;
    auto ldB = [&](int t) {
        int kr0 = k0 + t * KT + k2;
        pb0 = (kr0 < C_)     ? *(const float4*)&Bm[(size_t)kr0 * ldb + n0 + nq]       : make_float4(0,0,0,0);
        pb1 = (kr0 + 1 < C_) ? *(const float4*)&Bm[(size_t)(kr0 + 1) * ldb + n0 + nq] : make_float4(0,0,0,0);
    };
    auto stB = [&](int bufi) {
        __half* Bh = gsm + bufi * GRP + 2 * GA;
        *(uint32_t*)&Bh[(nq + 0) * 40 + k2] = f16pack(pb0.x, pb1.x);
        *(uint32_t*)&Bh[(nq + 1) * 40 + k2] = f16pack(pb0.y, pb1.y);
        *(uint32_t*)&Bh[(nq + 2) * 40 + k2] = f16pack(pb0.z, pb1.z);
        *(uint32_t*)&Bh[(nq + 3) * 40 + k2] = f16pack(pb0.w, pb1.w);
    };
    auto cpA = [&](int bufi, int t) {
        uint32_t b = base32 + (uint32_t)bufi * (GRP * 2) + offA;
        CPA16(b, Ah_p + t * KT);
        CPA16(b + GA * 2, Al_p + t * KT);
    };

    cpA(0, 0); CPCOMMIT();
    cpA(1, 1); CPCOMMIT();
    ldB(0); stB(0);
    ldB(1);
    CPWAIT1();
    gbar(barid);

    int cur = 0;
    for (int t = 0; t < T; t++) {
        int nx2 = cur + 2; if (nx2 >= 3) nx2 -= 3;
        if (t + 2 < T) cpA(nx2, t + 2);
        CPCOMMIT();
        tile_f16(gsm + cur * GRP, m0, nh, fr, fc, acc);
        if (t + 1 < T) {
            int nx = cur + 1; if (nx == 3) nx = 0;
            stB(nx);
            if (t + 2 < T) ldB(t + 2);
            CPWAIT1();
            gbar(barid);
        }
        cur = cur + 1; if (cur == 3) cur = 0;
    }
    store_acc(P, ldp, n0, m0, nh, fr, fc, acc);
}

// ---------------- the single fused persistent kernel ----------------
__global__ void __launch_bounds__(1024, 1)
fused_all(const float* __restrict__ x,
          const float* __restrict__ centroids,
          const float* __restrict__ W_hall,
          const float* __restrict__ b_hall,
          const float* __restrict__ W_sel,
          const float* __restrict__ b_sel,
          const float* __restrict__ W_cos,
          float* __restrict__ out, int writeFeat) {
    extern __shared__ __align__(16) __half dsm[];   // 4 groups * 3 buffers * GRP
    __shared__ float red[32];
    const int tid = threadIdx.x, bid = blockIdx.x;
    const int gid = tid >> 8, gt = tid & 255, barid = gid + 1;
    const int lane = tid & 31, wid = tid >> 5;
    __half* gsm = dsm + gid * 3 * GRP;

    // ===== S0: x -> fp16 hi/lo (only; norms are overlapped later) =====
    {
        const int i = bid * 1024 + tid;
        if (i < B_ * F_) {
            __half h, l;
            hilo1(x[i], h, l);
            g_xh[i] = h; g_xl[i] = l;
        }
    }
    grid_sync(0);

    // ===== S1: mega GEMMs (blocks 0..127) || centroid+x norms (blocks 128..147) =====
    {
        const int item = bid * 4 + gid;
        if (item < 64 * KSA) {
            const int t = item & 63, ks = item >> 6;
            const float* Bm; float* P; int Nn, n0, ldp;
            if (t < 16)      { Bm = centroids; P = g_p_dot[ks];  Nn = C_; n0 = t * 64;        ldp = CP; }
            else if (t < 32) { Bm = W_hall;    P = g_p_hall[ks]; Nn = C_; n0 = (t - 16) * 64; ldp = CP; }
            else             { Bm = W_sel;     P = g_p_sel[ks];  Nn = F_; n0 = (t - 32) * 64; ldp = F_; }
            group_nt_f16(g_xh, g_xl, F_, Bm, F_, P, ldp, Nn, n0, ks * 256, 256, gsm, gt, barid);
        } else if (bid >= 128) {
            const int gw = (bid - 128) * 32 + wid;   // 0..639
#pragma unroll
            for (int rep = 0; rep < 2; rep++) {
                const int r = gw + rep * 640;        // rows 0..1063
                if (r < C_) {
                    float s = warp_row_ss(centroids + (size_t)r * F_, lane);
                    if (lane == 0) g_cn2[r] = s;
                } else if (r < C_ + B_) {
                    float s = warp_row_ss(x + (size_t)(r - C_) * F_, lane);
                    if (lane == 0) g_xn2[r - C_] = s;
                }
            }
        }
    }
    grid_sync(1);

    // ===== S2: softmax etc (blocks 0..63) || W_cos norms (blocks 64..147) =====
    if (bid < B_) {
        const int b = bid;
        const int c0 = tid * 2;
        const bool val = (tid < 500);
        float hv0 = -1e30f, hv1 = -1e30f, d2m = 1e30f;
        if (val) {
            float2 dot = make_float2(0.f, 0.f), h = make_float2(0.f, 0.f);
#pragma unroll
            for (int s = 0; s < KSA; s++) {
                float2 d = *(const float2*)&g_p_dot[s][b * CP + c0];
                float2 hh = *(const float2*)&g_p_hall[s][b * CP + c0];
                dot.x += d.x; dot.y += d.y; h.x += hh.x; h.y += hh.y;
            }
            float2 bh = *(const float2*)&b_hall[c0];
            hv0 = h.x + bh.x; hv1 = h.y + bh.y;
            float xn2 = g_xn2[b];
            float d20 = xn2 + g_cn2[c0] - 2.f * dot.x;
            float d21 = xn2 + g_cn2[c0 + 1] - 2.f * dot.y;
            d2m = fminf(d20, d21);
        }
        float md2 = blk_min(d2m, red);
        float mh  = blk_max(fmaxf(hv0, hv1), red);
        float e0 = val ? __expf(hv0 - mh) : 0.f;
        float e1 = val ? __expf(hv1 - mh) : 0.f;
        float se = blk_sum(e0 + e1, red);
        if (tid < 512) {
            float inv = 1.f / se;
            float w0 = val ? e0 * inv : 0.f;
            float w1 = val ? e1 * inv : 0.f;
            uint32_t hp = f16pack(w0, w1);
            *(uint32_t*)&g_vmh[b * CP + c0] = hp;
            __half2 hh = *(__half2*)&hp;
            float l0 = w0 - __half2float(__low2half(hh));
            float l1 = w1 - __half2float(__high2half(hh));
            *(uint32_t*)&g_vml[b * CP + c0] = f16pack(l0, l1);
        }
        if (tid == 0) g_reach[b] = 10.f / sqrtf(fmaxf(md2, 1e-30f));
    } else {
        const int r = (bid - B_) * 32 + wid;   // 0..2687
        if (r < C_) {
            float s = warp_row_ss(W_cos + (size_t)r * F_, lane);
            if (lane == 0) g_wn[r] = sqrtf(s);
        }
    }
    grid_sync(2);

    // ===== S3: memory_feature = vm @ centroids  (512 items, klen 64) =====
    {
        const int item = bid * 4 + gid;
        if (item < 32 * KSM) {
            const int nt = item & 31, ks = item >> 5;
            group_nn_f16(g_vmh, g_vml, CP, centroids, F_, g_p_mem[ks], F_,
                         nt * 64, ks * 64, 64, gsm, gt, barid);
        }
    }
    grid_sync(3);

    // ===== S4: feat = reach*(x + tanh(sel)*mem) on 128 blocks (half row each) =====
    if (bid < 128) {
        const int b = bid >> 1;
        const int f = (bid & 1) * 1024 + tid;
        const float reach = g_reach[b];
        float mem = 0.f, sz = 0.f;
#pragma unroll
        for (int s = 0; s < KSM; s++) mem += g_p_mem[s][b * F_ + f];
#pragma unroll
        for (int s = 0; s < KSA; s++) sz  += g_p_sel[s][b * F_ + f];
        float sel  = tanhf(sz + b_sel[f]);
        float xv   = x[(size_t)b * F_ + f];
        float inf  = sel * mem;
        float feat = reach * (xv + inf);
        __half fh, fl;
        hilo1(feat, fh, fl);
        g_fh[b * F_ + f] = fh;
        g_fl[b * F_ + f] = fl;
        if (writeFeat) {
            out[64000 + b * F_ + f]  = xv;   // direct_feature
            out[195072 + b * F_ + f] = inf;  // infused_feature
        }
        float n2 = blk_sum(feat * feat, red);
        if (tid == 0) g_n2p[bid] = n2;
    }
    grid_sync(4);

    // ===== S5: cos logits GEMM feat @ W_cos^T (512 items) + scale reduce =====
    {
        const int item = bid * 4 + gid;
        if (item < 16 * KSC) {
            const int nt = item & 15, ks = item >> 4;
            group_nt_f16(g_fh, g_fl, F_, W_cos, F_, g_p_cos[ks], CP, C_,
                         nt * 64, ks * 64, 64, gsm, gt, barid);
        }
    }
    if (bid == NB - 1 && tid < B_) {
        float n2 = g_n2p[2 * tid] + g_n2p[2 * tid + 1];
        g_scale[tid] = 16.f / (1.f + sqrtf(n2));
    }
    grid_sync(5);

    // ===== S6: final scaled logits =====
    {
        const int i = bid * 1024 + tid;
        if (i < B_ * C_) {
            const int b = i / C_, c = i - b * C_;
            float s = 0.f;
#pragma unroll
            for (int ss = 0; ss < KSC; ss++) s += g_p_cos[ss][b * CP + c];
            out[i] = s * g_scale[b] / g_wn[c];
        }
    }
}

// ================= launch =================
#define DSM_BYTES (4 * 3 * GRP * 2)   // 184320 B

extern "C" void kernel_launch(void* const* d_in, const int* in_sizes, int n_in,
                              void* d_out, int out_size) {
    const float* x         = (const float*)d_in[0];
    const float* centroids = (const float*)d_in[1];
    const float* W_hall    = (const float*)d_in[2];
    const float* b_hall    = (const float*)d_in[3];
    const float* W_sel     = (const float*)d_in[4];
    const float* b_sel     = (const float*)d_in[5];
    const float* W_cos     = (const float*)d_in[6];
    float* out = (float*)d_out;

    cudaFuncSetAttribute(fused_all, cudaFuncAttributeMaxDynamicSharedMemorySize, DSM_BYTES);

    int writeFeat = (out_size >= 326144) ? 1 : 0;
    fused_all<<<NB, 1024, DSM_BYTES>>>(x, centroids, W_hall, b_hall, W_sel, b_sel, W_cos,
                                       out, writeFeat);
}